// round 2
// baseline (speedup 1.0000x reference)
#include <cuda_runtime.h>

#define BB    32
#define TT    12
#define NNODE 5000
#define CCH   8
#define EEDGE 5000
#define MEDGE 160000
#define LAMW  0.3f
#define EPSW  1e-8f

// normalized features, layout (node, b, 16)
__device__ float g_fhat[(size_t)NNODE * BB * 16];
// segment accumulators, layout (e, b)
__device__ float g_acc[(size_t)EEDGE * BB];
// per-b min/max (uint bits of non-negative floats)
__device__ unsigned g_mn[BB];
__device__ unsigned g_mx[BB];
// reciprocal counts
__device__ float g_icnt[EEDGE];

// ---------------------------------------------------------------------------
// Kernel 0: zero accumulators, init min/max, reciprocal counts
// ---------------------------------------------------------------------------
__global__ void init_kernel(const float* __restrict__ counts) {
    int i = blockIdx.x * blockDim.x + threadIdx.x;
    if (i < EEDGE * BB) g_acc[i] = 0.f;
    if (i < EEDGE)      g_icnt[i] = 1.0f / fmaxf(counts[i], 1.f);
    if (i < BB)         { g_mn[i] = 0x7f800000u; g_mx[i] = 0u; }
}

// ---------------------------------------------------------------------------
// Kernel 1: per-(b,n) mean/std over T, normalize 16-vector, store fhat
// ---------------------------------------------------------------------------
__global__ void feat_kernel(const float* __restrict__ x) {
    int tid = blockIdx.x * blockDim.x + threadIdx.x;
    if (tid >= BB * NNODE) return;
    int b = tid / NNODE;
    int n = tid - b * NNODE;

    float s[CCH], sq[CCH];
#pragma unroll
    for (int k = 0; k < CCH; k++) { s[k] = 0.f; sq[k] = 0.f; }

#pragma unroll
    for (int t = 0; t < TT; t++) {
        const float4* p = reinterpret_cast<const float4*>(
            x + (((size_t)b * TT + t) * NNODE + n) * CCH);
        float4 a = p[0];
        float4 c = p[1];
        float v[CCH] = {a.x, a.y, a.z, a.w, c.x, c.y, c.z, c.w};
#pragma unroll
        for (int k = 0; k < CCH; k++) {
            s[k] += v[k];
            sq[k] = fmaf(v[k], v[k], sq[k]);
        }
    }

    float f[16];
    float nrm2 = 0.f;
#pragma unroll
    for (int k = 0; k < CCH; k++) {
        float m   = s[k] * (1.0f / TT);
        float var = (sq[k] - (float)TT * m * m) * (1.0f / (TT - 1));
        float sd  = sqrtf(fmaxf(var, 0.f));
        f[k]       = m;
        f[CCH + k] = sd;
    }
#pragma unroll
    for (int k = 0; k < 16; k++) nrm2 = fmaf(f[k], f[k], nrm2);
    float inv = 1.0f / fmaxf(sqrtf(nrm2), EPSW);

    float4* o = reinterpret_cast<float4*>(g_fhat + ((size_t)n * BB + b) * 16);
#pragma unroll
    for (int q = 0; q < 4; q++) {
        float4 w;
        w.x = f[q * 4 + 0] * inv;
        w.y = f[q * 4 + 1] * inv;
        w.z = f[q * 4 + 2] * inv;
        w.w = f[q * 4 + 3] * inv;
        o[q] = w;
    }
}

// ---------------------------------------------------------------------------
// Kernel 2: each warp = 32 consecutive members, lane = batch b.
// Phase 1: fully unrolled independent dot computations (high MLP; v comes
//          from L1 because consecutive members share the center line-set).
// Phase 2: register-array segmented scan (warp-uniform branches), flush via
//          coalesced atomicAdd.
// ---------------------------------------------------------------------------
__global__ void sim_kernel(const int* __restrict__ members,
                           const int* __restrict__ eids) {
    int warp = (blockIdx.x * blockDim.x + threadIdx.x) >> 5;
    int lane = threadIdx.x & 31;
    int m0 = warp * 32;
    if (m0 >= MEDGE) return;   // MEDGE % 32 == 0: no tail

    int my_node = members[m0 + lane];
    int my_e    = eids[m0 + lane];

    float dots[32];
    int   es[32];

#pragma unroll
    for (int i = 0; i < 32; i++) {
        int node = __shfl_sync(0xffffffffu, my_node, i);
        int e    = __shfl_sync(0xffffffffu, my_e, i);
        es[i] = e;

        const float4* pu = reinterpret_cast<const float4*>(
            g_fhat + ((size_t)node * BB + lane) * 16);
        const float4* pv = reinterpret_cast<const float4*>(
            g_fhat + ((size_t)e * BB + lane) * 16);
        float4 u0 = pu[0], u1 = pu[1], u2 = pu[2], u3 = pu[3];
        float4 v0 = pv[0], v1 = pv[1], v2 = pv[2], v3 = pv[3];

        float d = u0.x * v0.x;
        d = fmaf(u0.y, v0.y, d); d = fmaf(u0.z, v0.z, d); d = fmaf(u0.w, v0.w, d);
        d = fmaf(u1.x, v1.x, d); d = fmaf(u1.y, v1.y, d); d = fmaf(u1.z, v1.z, d);
        d = fmaf(u1.w, v1.w, d); d = fmaf(u2.x, v2.x, d); d = fmaf(u2.y, v2.y, d);
        d = fmaf(u2.z, v2.z, d); d = fmaf(u2.w, v2.w, d); d = fmaf(u3.x, v3.x, d);
        d = fmaf(u3.y, v3.y, d); d = fmaf(u3.z, v3.z, d); d = fmaf(u3.w, v3.w, d);

        dots[i] = fminf(fmaxf(d, 0.f), 1.f);
    }

    int   cur  = es[0];
    float accs = dots[0];
#pragma unroll
    for (int i = 1; i < 32; i++) {
        if (es[i] != cur) {                        // warp-uniform branch
            atomicAdd(&g_acc[(size_t)cur * BB + lane], accs);
            cur  = es[i];
            accs = 0.f;
        }
        accs += dots[i];
    }
    atomicAdd(&g_acc[(size_t)cur * BB + lane], accs);
}

// ---------------------------------------------------------------------------
// Kernel 3a: per-b min/max. Warp-coalesced: lane = b, warp strides over e.
// ---------------------------------------------------------------------------
__global__ void minmax_kernel() {
    int wid  = threadIdx.x >> 5;
    int lane = threadIdx.x & 31;
    int nwarps_blk = blockDim.x >> 5;
    int warp_g  = blockIdx.x * nwarps_blk + wid;
    int nwarps  = gridDim.x * nwarps_blk;

    float mn = 1e30f, mx = 0.f;       // values are >= 0
    for (int e = warp_g; e < EEDGE; e += nwarps) {
        float s = g_acc[(size_t)e * BB + lane] * g_icnt[e];
        mn = fminf(mn, s);
        mx = fmaxf(mx, s);
    }

    __shared__ float smn[8][32], smx[8][32];
    smn[wid][lane] = mn;
    smx[wid][lane] = mx;
    __syncthreads();
    if (wid == 0) {
        for (int i = 1; i < nwarps_blk; i++) {
            mn = fminf(mn, smn[i][lane]);
            mx = fmaxf(mx, smx[i][lane]);
        }
        atomicMin(&g_mn[lane], __float_as_uint(mn));
        atomicMax(&g_mx[lane], __float_as_uint(mx));
    }
}

// ---------------------------------------------------------------------------
// Kernel 3b: scale + write output (coalesced along e)
// ---------------------------------------------------------------------------
__global__ void scale_kernel(const float* __restrict__ W,
                             float* __restrict__ out) {
    int idx = blockIdx.x * blockDim.x + threadIdx.x;
    if (idx >= BB * EEDGE) return;
    int b = idx / EEDGE;
    int e = idx - b * EEDGE;

    float mn  = __uint_as_float(g_mn[b]);
    float mx  = __uint_as_float(g_mx[b]);
    float inv = LAMW / (mx - mn + EPSW);

    float s = g_acc[(size_t)e * BB + b] * g_icnt[e];
    out[idx] = W[e] * (1.f + (s - mn) * inv);
}

// ---------------------------------------------------------------------------
extern "C" void kernel_launch(void* const* d_in, const int* in_sizes, int n_in,
                              void* d_out, int out_size) {
    const float* x_raw   = (const float*)d_in[0];
    const float* W       = (const float*)d_in[1];
    const int*   members = (const int*)d_in[2];
    // d_in[3] = centers (== arange(E), unused)
    const int*   eids    = (const int*)d_in[4];
    const float* counts  = (const float*)d_in[5];
    float*       out     = (float*)d_out;

    init_kernel<<<(EEDGE * BB + 255) / 256, 256>>>(counts);
    feat_kernel<<<(BB * NNODE + 255) / 256, 256>>>(x_raw);

    int warps  = (MEDGE + 31) / 32;                 // 5000
    int blocks = (warps * 32 + 255) / 256;          // 625
    sim_kernel<<<blocks, 256>>>(members, eids);

    minmax_kernel<<<40, 256>>>();
    scale_kernel<<<(BB * EEDGE + 255) / 256, 256>>>(W, out);
}

// round 3
// speedup vs baseline: 2.4081x; 2.4081x over previous
#include <cuda_runtime.h>

#define BB    32
#define TT    12
#define NNODE 5000
#define CCH   8
#define EEDGE 5000
#define MEDGE 160000
#define LAMW  0.3f
#define EPSW  1e-8f

// normalized features, layout (node, b, 16) float
__device__ float g_fhat[(size_t)NNODE * BB * 16];
// segment accumulators, layout (e, b)
__device__ float g_acc[(size_t)EEDGE * BB];
// per-b min/max (uint bits of non-negative floats)
__device__ unsigned g_mn[BB];
__device__ unsigned g_mx[BB];
// reciprocal counts
__device__ float g_icnt[EEDGE];

// ---------------------------------------------------------------------------
// Kernel 0: zero accumulators, init min/max, reciprocal counts
// ---------------------------------------------------------------------------
__global__ void init_kernel(const float* __restrict__ counts) {
    int i = blockIdx.x * blockDim.x + threadIdx.x;
    if (i < EEDGE * BB) g_acc[i] = 0.f;
    if (i < EEDGE)      g_icnt[i] = 1.0f / fmaxf(counts[i], 1.f);
    if (i < BB)         { g_mn[i] = 0x7f800000u; g_mx[i] = 0u; }
}

// ---------------------------------------------------------------------------
// Kernel 1: per-(b,n) mean/std over T, normalize 16-vector, store fhat
// ---------------------------------------------------------------------------
__global__ void feat_kernel(const float* __restrict__ x) {
    int tid = blockIdx.x * blockDim.x + threadIdx.x;
    if (tid >= BB * NNODE) return;
    int b = tid / NNODE;
    int n = tid - b * NNODE;

    float s[CCH], sq[CCH];
#pragma unroll
    for (int k = 0; k < CCH; k++) { s[k] = 0.f; sq[k] = 0.f; }

#pragma unroll
    for (int t = 0; t < TT; t++) {
        const float4* p = reinterpret_cast<const float4*>(
            x + (((size_t)b * TT + t) * NNODE + n) * CCH);
        float4 a = p[0];
        float4 c = p[1];
        float v[CCH] = {a.x, a.y, a.z, a.w, c.x, c.y, c.z, c.w};
#pragma unroll
        for (int k = 0; k < CCH; k++) {
            s[k] += v[k];
            sq[k] = fmaf(v[k], v[k], sq[k]);
        }
    }

    float f[16];
    float nrm2 = 0.f;
#pragma unroll
    for (int k = 0; k < CCH; k++) {
        float m   = s[k] * (1.0f / TT);
        float var = (sq[k] - (float)TT * m * m) * (1.0f / (TT - 1));
        float sd  = sqrtf(fmaxf(var, 0.f));
        f[k]       = m;
        f[CCH + k] = sd;
    }
#pragma unroll
    for (int k = 0; k < 16; k++) nrm2 = fmaf(f[k], f[k], nrm2);
    float inv = 1.0f / fmaxf(sqrtf(nrm2), EPSW);

    float4* o = reinterpret_cast<float4*>(g_fhat + ((size_t)n * BB + b) * 16);
#pragma unroll
    for (int q = 0; q < 4; q++) {
        float4 w;
        w.x = f[q * 4 + 0] * inv;
        w.y = f[q * 4 + 1] * inv;
        w.z = f[q * 4 + 2] * inv;
        w.w = f[q * 4 + 3] * inv;
        o[q] = w;
    }
}

// ---------------------------------------------------------------------------
// Kernel 2: each warp = 32 consecutive members (sorted by edge id).
// Fully-coalesced record reads: instruction q reads 512 contiguous bytes
// (lane l gets channels (l&3)*4..+4 of batch b=q*8+(l>>2)).
// Dot completed via 4-lane butterfly; lane owns b=(l&3)*8+(l>>2).
// Center vector v register-resident across each sorted segment run.
// ---------------------------------------------------------------------------
__global__ void sim_kernel(const int* __restrict__ members,
                           const int* __restrict__ eids) {
    int warp = (blockIdx.x * blockDim.x + threadIdx.x) >> 5;
    int lane = threadIdx.x & 31;
    int m0 = warp * 32;
    if (m0 >= MEDGE) return;              // MEDGE % 32 == 0: no tail

    int r = lane & 3;                     // selects owned q at flush
    int j = lane >> 2;
    int my_b = r * 8 + j;                 // owned batch index (bijection)

    int my_node = members[m0 + lane];
    int my_e    = eids[m0 + lane];

    float4 v0, v1, v2, v3;                // v slice per q
    int   cur_e = -1;
    float acc   = 0.f;

    for (int i = 0; i < 32; i++) {
        int node = __shfl_sync(0xffffffffu, my_node, i);
        int e    = __shfl_sync(0xffffffffu, my_e, i);

        if (e != cur_e) {
            if (cur_e >= 0)
                atomicAdd(&g_acc[(size_t)cur_e * BB + my_b], acc);
            acc = 0.f;
            const float4* pv = reinterpret_cast<const float4*>(
                g_fhat + (size_t)e * (BB * 16));
            v0 = pv[lane]; v1 = pv[32 + lane];
            v2 = pv[64 + lane]; v3 = pv[96 + lane];
            cur_e = e;
        }

        const float4* pu = reinterpret_cast<const float4*>(
            g_fhat + (size_t)node * (BB * 16));
        float4 u0 = pu[lane], u1 = pu[32 + lane];
        float4 u2 = pu[64 + lane], u3 = pu[96 + lane];

        float d0 = u0.x * v0.x;
        d0 = fmaf(u0.y, v0.y, d0); d0 = fmaf(u0.z, v0.z, d0); d0 = fmaf(u0.w, v0.w, d0);
        float d1 = u1.x * v1.x;
        d1 = fmaf(u1.y, v1.y, d1); d1 = fmaf(u1.z, v1.z, d1); d1 = fmaf(u1.w, v1.w, d1);
        float d2 = u2.x * v2.x;
        d2 = fmaf(u2.y, v2.y, d2); d2 = fmaf(u2.z, v2.z, d2); d2 = fmaf(u2.w, v2.w, d2);
        float d3 = u3.x * v3.x;
        d3 = fmaf(u3.y, v3.y, d3); d3 = fmaf(u3.z, v3.z, d3); d3 = fmaf(u3.w, v3.w, d3);

        // butterfly over the 4 lanes sharing (q, j): full dots materialize
        d0 += __shfl_xor_sync(0xffffffffu, d0, 1);
        d1 += __shfl_xor_sync(0xffffffffu, d1, 1);
        d2 += __shfl_xor_sync(0xffffffffu, d2, 1);
        d3 += __shfl_xor_sync(0xffffffffu, d3, 1);
        d0 += __shfl_xor_sync(0xffffffffu, d0, 2);
        d1 += __shfl_xor_sync(0xffffffffu, d1, 2);
        d2 += __shfl_xor_sync(0xffffffffu, d2, 2);
        d3 += __shfl_xor_sync(0xffffffffu, d3, 2);

        // lane keeps the dot for its owned b = r*8 + j  (q == r)
        float d = (r == 0) ? d0 : (r == 1) ? d1 : (r == 2) ? d2 : d3;
        acc += fminf(fmaxf(d, 0.f), 1.f);
    }
    atomicAdd(&g_acc[(size_t)cur_e * BB + my_b], acc);
}

// ---------------------------------------------------------------------------
// Kernel 3a: per-b min/max. lane = b, warp strides over e. Wide grid.
// ---------------------------------------------------------------------------
__global__ void minmax_kernel() {
    int wid  = threadIdx.x >> 5;
    int lane = threadIdx.x & 31;
    int nwarps_blk = blockDim.x >> 5;
    int warp_g  = blockIdx.x * nwarps_blk + wid;
    int nwarps  = gridDim.x * nwarps_blk;

    float mn = 1e30f, mx = 0.f;           // values are >= 0
    for (int e = warp_g; e < EEDGE; e += nwarps) {
        float s = g_acc[(size_t)e * BB + lane] * g_icnt[e];
        mn = fminf(mn, s);
        mx = fmaxf(mx, s);
    }

    __shared__ float smn[8][32], smx[8][32];
    smn[wid][lane] = mn;
    smx[wid][lane] = mx;
    __syncthreads();
    if (wid == 0) {
        for (int i = 1; i < nwarps_blk; i++) {
            mn = fminf(mn, smn[i][lane]);
            mx = fmaxf(mx, smx[i][lane]);
        }
        atomicMin(&g_mn[lane], __float_as_uint(mn));
        atomicMax(&g_mx[lane], __float_as_uint(mx));
    }
}

// ---------------------------------------------------------------------------
// Kernel 3b: scale + write output (coalesced along e)
// ---------------------------------------------------------------------------
__global__ void scale_kernel(const float* __restrict__ W,
                             float* __restrict__ out) {
    int idx = blockIdx.x * blockDim.x + threadIdx.x;
    if (idx >= BB * EEDGE) return;
    int b = idx / EEDGE;
    int e = idx - b * EEDGE;

    float mn  = __uint_as_float(g_mn[b]);
    float mx  = __uint_as_float(g_mx[b]);
    float inv = LAMW / (mx - mn + EPSW);

    float s = g_acc[(size_t)e * BB + b] * g_icnt[e];
    out[idx] = W[e] * (1.f + (s - mn) * inv);
}

// ---------------------------------------------------------------------------
extern "C" void kernel_launch(void* const* d_in, const int* in_sizes, int n_in,
                              void* d_out, int out_size) {
    const float* x_raw   = (const float*)d_in[0];
    const float* W       = (const float*)d_in[1];
    const int*   members = (const int*)d_in[2];
    // d_in[3] = centers (== arange(E), unused)
    const int*   eids    = (const int*)d_in[4];
    const float* counts  = (const float*)d_in[5];
    float*       out     = (float*)d_out;

    init_kernel<<<(EEDGE * BB + 255) / 256, 256>>>(counts);
    feat_kernel<<<(BB * NNODE + 255) / 256, 256>>>(x_raw);

    int warps  = (MEDGE + 31) / 32;                 // 5000
    int blocks = (warps * 32 + 255) / 256;          // 625
    sim_kernel<<<blocks, 256>>>(members, eids);

    minmax_kernel<<<157, 256>>>();
    scale_kernel<<<(BB * EEDGE + 255) / 256, 256>>>(W, out);
}

// round 4
// speedup vs baseline: 3.1521x; 1.3090x over previous
#include <cuda_runtime.h>
#include <cuda_fp16.h>

#define BB    32
#define TT    12
#define NNODE 5000
#define CCH   8
#define EEDGE 5000
#define MEDGE 160000
#define LAMW  0.3f
#define EPSW  1e-8f

// normalized features in fp16.
// Record per node = 1024B = 64 uint4. Within record, byte address of
// (b, c) is q*512 + l*16 + (c&7)*2 where q=b>>4, l=(b&15)*2 + (c>>3).
__device__ uint4 g_fhat[(size_t)NNODE * 64];
// segment accumulators, layout (b, e)  [transposed]
__device__ float g_acc[(size_t)BB * EEDGE];
// reciprocal counts
__device__ float g_icnt[EEDGE];

// ---------------------------------------------------------------------------
// Kernel 0: zero accumulators (float4), reciprocal counts
// ---------------------------------------------------------------------------
__global__ void init_kernel(const float* __restrict__ counts) {
    int i = blockIdx.x * blockDim.x + threadIdx.x;
    if (i < (BB * EEDGE) / 4) reinterpret_cast<float4*>(g_acc)[i] =
        make_float4(0.f, 0.f, 0.f, 0.f);
    if (i < EEDGE) g_icnt[i] = 1.0f / fmaxf(counts[i], 1.f);
}

// ---------------------------------------------------------------------------
// Kernel 1: per-(b,n) mean/std over T, normalize 16-vector, store fp16 fhat
// ---------------------------------------------------------------------------
__global__ void feat_kernel(const float* __restrict__ x) {
    int tid = blockIdx.x * blockDim.x + threadIdx.x;
    if (tid >= BB * NNODE) return;
    int b = tid / NNODE;
    int n = tid - b * NNODE;

    float s[CCH], sq[CCH];
#pragma unroll
    for (int k = 0; k < CCH; k++) { s[k] = 0.f; sq[k] = 0.f; }

#pragma unroll
    for (int t = 0; t < TT; t++) {
        const float4* p = reinterpret_cast<const float4*>(
            x + (((size_t)b * TT + t) * NNODE + n) * CCH);
        float4 a = p[0];
        float4 c = p[1];
        float v[CCH] = {a.x, a.y, a.z, a.w, c.x, c.y, c.z, c.w};
#pragma unroll
        for (int k = 0; k < CCH; k++) {
            s[k] += v[k];
            sq[k] = fmaf(v[k], v[k], sq[k]);
        }
    }

    float f[16];
    float nrm2 = 0.f;
#pragma unroll
    for (int k = 0; k < CCH; k++) {
        float m   = s[k] * (1.0f / TT);
        float var = (sq[k] - (float)TT * m * m) * (1.0f / (TT - 1));
        float sd  = sqrtf(fmaxf(var, 0.f));
        f[k]       = m;
        f[CCH + k] = sd;
    }
#pragma unroll
    for (int k = 0; k < 16; k++) nrm2 = fmaf(f[k], f[k], nrm2);
    float inv = 1.0f / fmaxf(sqrtf(nrm2), EPSW);

    // pack 16 halves: chunk0 = channels 0..7, chunk1 = channels 8..15
    // destination: record n, byte offset q*512 + (b&15)*32, q = b>>4
    union { __half2 h2[8]; uint4 u4[2]; } pk;
#pragma unroll
    for (int k = 0; k < 8; k++)
        pk.h2[k] = __floats2half2_rn(f[2 * k] * inv, f[2 * k + 1] * inv);

    int q = b >> 4;
    uint4* dst = g_fhat + (size_t)n * 64 + q * 32 + (b & 15) * 2;
    dst[0] = pk.u4[0];
    dst[1] = pk.u4[1];
}

// ---------------------------------------------------------------------------
// Kernel 2: each warp = 32 consecutive members (sorted by edge id).
// fp16 records: 2 fully-coalesced LDG.128 per member (1024B contiguous).
// Instr q (q=0,1), lane l gets b=q*16+(l>>1), channels (l&1)*8..+8.
// fp32 dot partials; xor-1 butterfly completes each dot.
// Lane owns b = (l&1)*16 + (l>>1). v converted to fp32 once per segment.
// ---------------------------------------------------------------------------
__global__ void sim_kernel(const int* __restrict__ members,
                           const int* __restrict__ eids) {
    int warp = (blockIdx.x * blockDim.x + threadIdx.x) >> 5;
    int lane = threadIdx.x & 31;
    int m0 = warp * 32;
    if (m0 >= MEDGE) return;              // MEDGE % 32 == 0: no tail

    int my_b = ((lane & 1) << 4) | (lane >> 1);

    int my_node = members[m0 + lane];
    int my_e    = eids[m0 + lane];

    float vf0[8], vf1[8];                 // fp32 center slices (per q)
    int   cur_e = -1;
    float acc   = 0.f;

    for (int i = 0; i < 32; i++) {
        int node = __shfl_sync(0xffffffffu, my_node, i);
        int e    = __shfl_sync(0xffffffffu, my_e, i);

        if (e != cur_e) {
            if (cur_e >= 0)
                atomicAdd(&g_acc[(size_t)my_b * EEDGE + cur_e], acc);
            acc = 0.f;
            const uint4* pv = g_fhat + (size_t)e * 64;
            union { uint4 u; __half2 h[4]; } a0, a1;
            a0.u = pv[lane];
            a1.u = pv[32 + lane];
#pragma unroll
            for (int k = 0; k < 4; k++) {
                float2 t0 = __half22float2(a0.h[k]);
                float2 t1 = __half22float2(a1.h[k]);
                vf0[2 * k] = t0.x; vf0[2 * k + 1] = t0.y;
                vf1[2 * k] = t1.x; vf1[2 * k + 1] = t1.y;
            }
            cur_e = e;
        }

        const uint4* pu = g_fhat + (size_t)node * 64;
        union { uint4 u; __half2 h[4]; } b0, b1;
        b0.u = pu[lane];
        b1.u = pu[32 + lane];

        float d0, d1;
        {
            float2 t = __half22float2(b0.h[0]);
            d0 = t.x * vf0[0]; d0 = fmaf(t.y, vf0[1], d0);
            t = __half22float2(b0.h[1]);
            d0 = fmaf(t.x, vf0[2], d0); d0 = fmaf(t.y, vf0[3], d0);
            t = __half22float2(b0.h[2]);
            d0 = fmaf(t.x, vf0[4], d0); d0 = fmaf(t.y, vf0[5], d0);
            t = __half22float2(b0.h[3]);
            d0 = fmaf(t.x, vf0[6], d0); d0 = fmaf(t.y, vf0[7], d0);

            t = __half22float2(b1.h[0]);
            d1 = t.x * vf1[0]; d1 = fmaf(t.y, vf1[1], d1);
            t = __half22float2(b1.h[1]);
            d1 = fmaf(t.x, vf1[2], d1); d1 = fmaf(t.y, vf1[3], d1);
            t = __half22float2(b1.h[2]);
            d1 = fmaf(t.x, vf1[4], d1); d1 = fmaf(t.y, vf1[5], d1);
            t = __half22float2(b1.h[3]);
            d1 = fmaf(t.x, vf1[6], d1); d1 = fmaf(t.y, vf1[7], d1);
        }

        // complete dots across channel-half pairs
        d0 += __shfl_xor_sync(0xffffffffu, d0, 1);
        d1 += __shfl_xor_sync(0xffffffffu, d1, 1);

        float d = (lane & 1) ? d1 : d0;   // owned q == lane&1
        acc += fminf(fmaxf(d, 0.f), 1.f);
    }
    atomicAdd(&g_acc[(size_t)my_b * EEDGE + cur_e], acc);
}

// ---------------------------------------------------------------------------
// Kernel 3: fused per-b min/max + scale. One block per b; rows contiguous.
// ---------------------------------------------------------------------------
__global__ void finalize_kernel(const float* __restrict__ W,
                                float* __restrict__ out) {
    int b = blockIdx.x;
    const float* row = g_acc + (size_t)b * EEDGE;

    float mn = 1e30f, mx = 0.f;           // values >= 0
    for (int e = threadIdx.x; e < EEDGE; e += blockDim.x) {
        float s = row[e] * g_icnt[e];
        mn = fminf(mn, s);
        mx = fmaxf(mx, s);
    }
#pragma unroll
    for (int o = 16; o; o >>= 1) {
        mn = fminf(mn, __shfl_xor_sync(0xffffffffu, mn, o));
        mx = fmaxf(mx, __shfl_xor_sync(0xffffffffu, mx, o));
    }
    __shared__ float smn[16], smx[16];
    int wid = threadIdx.x >> 5, lanid = threadIdx.x & 31;
    if (lanid == 0) { smn[wid] = mn; smx[wid] = mx; }
    __syncthreads();
    int nw = blockDim.x >> 5;
    if (threadIdx.x == 0) {
        float a = smn[0], c = smx[0];
        for (int i = 1; i < nw; i++) {
            a = fminf(a, smn[i]);
            c = fmaxf(c, smx[i]);
        }
        smn[0] = a; smx[0] = c;
    }
    __syncthreads();
    mn = smn[0];
    mx = smx[0];
    float inv = LAMW / (mx - mn + EPSW);

    for (int e = threadIdx.x; e < EEDGE; e += blockDim.x) {
        float s = row[e] * g_icnt[e];
        out[(size_t)b * EEDGE + e] = W[e] * (1.f + (s - mn) * inv);
    }
}

// ---------------------------------------------------------------------------
extern "C" void kernel_launch(void* const* d_in, const int* in_sizes, int n_in,
                              void* d_out, int out_size) {
    const float* x_raw   = (const float*)d_in[0];
    const float* W       = (const float*)d_in[1];
    const int*   members = (const int*)d_in[2];
    // d_in[3] = centers (== arange(E), unused)
    const int*   eids    = (const int*)d_in[4];
    const float* counts  = (const float*)d_in[5];
    float*       out     = (float*)d_out;

    init_kernel<<<(BB * EEDGE / 4 + 255) / 256, 256>>>(counts);
    feat_kernel<<<(BB * NNODE + 255) / 256, 256>>>(x_raw);

    int warps  = (MEDGE + 31) / 32;                 // 5000
    int blocks = (warps * 32 + 255) / 256;          // 625
    sim_kernel<<<blocks, 256>>>(members, eids);

    finalize_kernel<<<BB, 512>>>(W, out);
}

// round 5
// speedup vs baseline: 3.4546x; 1.0960x over previous
#include <cuda_runtime.h>
#include <cuda_fp16.h>

#define BB    32
#define TT    12
#define NNODE 5000
#define CCH   8
#define EEDGE 5000
#define MEDGE 160000
#define LAMW  0.3f
#define EPSW  1e-8f
#define NCHUNK 5              // minmax blocks per b (5*1024 >= 5000)

// normalized features in fp16. Record per node = 1024B = 64 uint4.
__device__ uint4 g_fhat[(size_t)NNODE * 64];
// segment accumulators, layout (b, e)
__device__ float g_acc[(size_t)BB * EEDGE];
// reciprocal counts
__device__ float g_icnt[EEDGE];
// stage-1 partial min/max, layout (b, chunk)
__device__ float g_pmn[BB * NCHUNK];
__device__ float g_pmx[BB * NCHUNK];

// ---------------------------------------------------------------------------
// Kernel 1: feat + (folded) zero-acc + icnt
// ---------------------------------------------------------------------------
__global__ void feat_kernel(const float* __restrict__ x,
                            const float* __restrict__ counts) {
    int tid = blockIdx.x * blockDim.x + threadIdx.x;
    if (tid < (BB * EEDGE) / 4)
        reinterpret_cast<float4*>(g_acc)[tid] = make_float4(0.f, 0.f, 0.f, 0.f);
    if (tid < EEDGE)
        g_icnt[tid] = 1.0f / fmaxf(counts[tid], 1.f);
    if (tid >= BB * NNODE) return;

    int b = tid / NNODE;
    int n = tid - b * NNODE;

    float s[CCH], sq[CCH];
#pragma unroll
    for (int k = 0; k < CCH; k++) { s[k] = 0.f; sq[k] = 0.f; }

#pragma unroll
    for (int t = 0; t < TT; t++) {
        const float4* p = reinterpret_cast<const float4*>(
            x + (((size_t)b * TT + t) * NNODE + n) * CCH);
        float4 a = p[0];
        float4 c = p[1];
        float v[CCH] = {a.x, a.y, a.z, a.w, c.x, c.y, c.z, c.w};
#pragma unroll
        for (int k = 0; k < CCH; k++) {
            s[k] += v[k];
            sq[k] = fmaf(v[k], v[k], sq[k]);
        }
    }

    float f[16];
    float nrm2 = 0.f;
#pragma unroll
    for (int k = 0; k < CCH; k++) {
        float m   = s[k] * (1.0f / TT);
        float var = (sq[k] - (float)TT * m * m) * (1.0f / (TT - 1));
        float sd  = sqrtf(fmaxf(var, 0.f));
        f[k]       = m;
        f[CCH + k] = sd;
    }
#pragma unroll
    for (int k = 0; k < 16; k++) nrm2 = fmaf(f[k], f[k], nrm2);
    float inv = 1.0f / fmaxf(sqrtf(nrm2), EPSW);

    union { __half2 h2[8]; uint4 u4[2]; } pk;
#pragma unroll
    for (int k = 0; k < 8; k++)
        pk.h2[k] = __floats2half2_rn(f[2 * k] * inv, f[2 * k + 1] * inv);

    int q = b >> 4;
    uint4* dst = g_fhat + (size_t)n * 64 + q * 32 + (b & 15) * 2;
    dst[0] = pk.u4[0];
    dst[1] = pk.u4[1];
}

// ---------------------------------------------------------------------------
// Kernel 2: sim (unchanged from round 4 — near its LTS floor)
// ---------------------------------------------------------------------------
__global__ void sim_kernel(const int* __restrict__ members,
                           const int* __restrict__ eids) {
    int warp = (blockIdx.x * blockDim.x + threadIdx.x) >> 5;
    int lane = threadIdx.x & 31;
    int m0 = warp * 32;
    if (m0 >= MEDGE) return;

    int my_b = ((lane & 1) << 4) | (lane >> 1);

    int my_node = members[m0 + lane];
    int my_e    = eids[m0 + lane];

    float vf0[8], vf1[8];
    int   cur_e = -1;
    float acc   = 0.f;

    for (int i = 0; i < 32; i++) {
        int node = __shfl_sync(0xffffffffu, my_node, i);
        int e    = __shfl_sync(0xffffffffu, my_e, i);

        if (e != cur_e) {
            if (cur_e >= 0)
                atomicAdd(&g_acc[(size_t)my_b * EEDGE + cur_e], acc);
            acc = 0.f;
            const uint4* pv = g_fhat + (size_t)e * 64;
            union { uint4 u; __half2 h[4]; } a0, a1;
            a0.u = pv[lane];
            a1.u = pv[32 + lane];
#pragma unroll
            for (int k = 0; k < 4; k++) {
                float2 t0 = __half22float2(a0.h[k]);
                float2 t1 = __half22float2(a1.h[k]);
                vf0[2 * k] = t0.x; vf0[2 * k + 1] = t0.y;
                vf1[2 * k] = t1.x; vf1[2 * k + 1] = t1.y;
            }
            cur_e = e;
        }

        const uint4* pu = g_fhat + (size_t)node * 64;
        union { uint4 u; __half2 h[4]; } b0, b1;
        b0.u = pu[lane];
        b1.u = pu[32 + lane];

        float d0, d1;
        {
            float2 t = __half22float2(b0.h[0]);
            d0 = t.x * vf0[0]; d0 = fmaf(t.y, vf0[1], d0);
            t = __half22float2(b0.h[1]);
            d0 = fmaf(t.x, vf0[2], d0); d0 = fmaf(t.y, vf0[3], d0);
            t = __half22float2(b0.h[2]);
            d0 = fmaf(t.x, vf0[4], d0); d0 = fmaf(t.y, vf0[5], d0);
            t = __half22float2(b0.h[3]);
            d0 = fmaf(t.x, vf0[6], d0); d0 = fmaf(t.y, vf0[7], d0);

            t = __half22float2(b1.h[0]);
            d1 = t.x * vf1[0]; d1 = fmaf(t.y, vf1[1], d1);
            t = __half22float2(b1.h[1]);
            d1 = fmaf(t.x, vf1[2], d1); d1 = fmaf(t.y, vf1[3], d1);
            t = __half22float2(b1.h[2]);
            d1 = fmaf(t.x, vf1[4], d1); d1 = fmaf(t.y, vf1[5], d1);
            t = __half22float2(b1.h[3]);
            d1 = fmaf(t.x, vf1[6], d1); d1 = fmaf(t.y, vf1[7], d1);
        }

        d0 += __shfl_xor_sync(0xffffffffu, d0, 1);
        d1 += __shfl_xor_sync(0xffffffffu, d1, 1);

        float d = (lane & 1) ? d1 : d0;
        acc += fminf(fmaxf(d, 0.f), 1.f);
    }
    atomicAdd(&g_acc[(size_t)my_b * EEDGE + cur_e], acc);
}

// ---------------------------------------------------------------------------
// Kernel 3a: stage-1 min/max partials. Grid (NCHUNK, BB), block 256.
// One float4 per thread; block-reduce; NO atomics.
// ---------------------------------------------------------------------------
__global__ void minmax_kernel() {
    int b     = blockIdx.y;
    int chunk = blockIdx.x;
    int i4    = chunk * 256 + threadIdx.x;      // float4 index within row

    float mn = 1e30f, mx = 0.f;                 // values >= 0
    if (i4 < EEDGE / 4) {
        float4 a = reinterpret_cast<const float4*>(g_acc + (size_t)b * EEDGE)[i4];
        float4 c = reinterpret_cast<const float4*>(g_icnt)[i4];
        float s0 = a.x * c.x, s1 = a.y * c.y, s2 = a.z * c.z, s3 = a.w * c.w;
        mn = fminf(fminf(s0, s1), fminf(s2, s3));
        mx = fmaxf(fmaxf(s0, s1), fmaxf(s2, s3));
    }
#pragma unroll
    for (int o = 16; o; o >>= 1) {
        mn = fminf(mn, __shfl_xor_sync(0xffffffffu, mn, o));
        mx = fmaxf(mx, __shfl_xor_sync(0xffffffffu, mx, o));
    }
    __shared__ float smn[8], smx[8];
    int wid = threadIdx.x >> 5, lane = threadIdx.x & 31;
    if (lane == 0) { smn[wid] = mn; smx[wid] = mx; }
    __syncthreads();
    if (threadIdx.x == 0) {
#pragma unroll
        for (int i = 1; i < 8; i++) {
            mn = fminf(mn, smn[i]);
            mx = fmaxf(mx, smx[i]);
        }
        g_pmn[b * NCHUNK + chunk] = mn;
        g_pmx[b * NCHUNK + chunk] = mx;
    }
}

// ---------------------------------------------------------------------------
// Kernel 3b: scale + write. Grid (NCHUNK, BB), block 256, one float4/thread.
// ---------------------------------------------------------------------------
__global__ void scale_kernel(const float* __restrict__ W,
                             float* __restrict__ out) {
    int b  = blockIdx.y;
    int i4 = blockIdx.x * 256 + threadIdx.x;
    if (i4 >= EEDGE / 4) return;

    float mn = g_pmn[b * NCHUNK];
    float mx = g_pmx[b * NCHUNK];
#pragma unroll
    for (int i = 1; i < NCHUNK; i++) {
        mn = fminf(mn, g_pmn[b * NCHUNK + i]);
        mx = fmaxf(mx, g_pmx[b * NCHUNK + i]);
    }
    float inv = LAMW / (mx - mn + EPSW);

    float4 a = reinterpret_cast<const float4*>(g_acc + (size_t)b * EEDGE)[i4];
    float4 c = reinterpret_cast<const float4*>(g_icnt)[i4];
    float4 w = reinterpret_cast<const float4*>(W)[i4];

    float4 o;
    o.x = w.x * (1.f + (a.x * c.x - mn) * inv);
    o.y = w.y * (1.f + (a.y * c.y - mn) * inv);
    o.z = w.z * (1.f + (a.z * c.z - mn) * inv);
    o.w = w.w * (1.f + (a.w * c.w - mn) * inv);
    reinterpret_cast<float4*>(out + (size_t)b * EEDGE)[i4] = o;
}

// ---------------------------------------------------------------------------
extern "C" void kernel_launch(void* const* d_in, const int* in_sizes, int n_in,
                              void* d_out, int out_size) {
    const float* x_raw   = (const float*)d_in[0];
    const float* W       = (const float*)d_in[1];
    const int*   members = (const int*)d_in[2];
    // d_in[3] = centers (== arange(E), unused)
    const int*   eids    = (const int*)d_in[4];
    const float* counts  = (const float*)d_in[5];
    float*       out     = (float*)d_out;

    feat_kernel<<<(BB * NNODE + 255) / 256, 256>>>(x_raw, counts);

    int warps  = (MEDGE + 31) / 32;                 // 5000
    int blocks = (warps * 32 + 255) / 256;          // 625
    sim_kernel<<<blocks, 256>>>(members, eids);

    dim3 fin_grid(NCHUNK, BB);
    minmax_kernel<<<fin_grid, 256>>>();
    scale_kernel<<<fin_grid, 256>>>(W, out);
}